// round 9
// baseline (speedup 1.0000x reference)
#include <cuda_runtime.h>
#include <math.h>

#define B_  512
#define T_  512
#define H_  100
#define DI_ 101
#define DO_ 2

typedef unsigned long long ull;

__device__ float g_xp[(size_t)B_ * T_ * H_];   // holds 0.1*(inp@Wx^T + b)

__device__ __forceinline__ ull fma2(ull a, ull b, ull c) {
    ull d;
    asm("fma.rn.f32x2 %0, %1, %2, %3;" : "=l"(d) : "l"(a), "l"(b), "l"(c));
    return d;
}
__device__ __forceinline__ ull add2(ull a, ull b) {
    ull d;
    asm("add.rn.f32x2 %0, %1, %2;" : "=l"(d) : "l"(a), "l"(b));
    return d;
}
__device__ __forceinline__ ull dup2(float a) {
    ull d;
    asm("mov.b64 %0, {%1, %1};" : "=l"(d) : "f"(a));
    return d;
}
__device__ __forceinline__ float2 u2f(ull v) {
    float2 f;
    asm("mov.b64 {%0, %1}, %2;" : "=f"(f.x), "=f"(f.y) : "l"(v));
    return f;
}
__device__ __forceinline__ void cp_async4(unsigned smem_addr, const void* gptr) {
    asm volatile("cp.async.ca.shared.global [%0], [%1], 4;"
                 :: "r"(smem_addr), "l"(gptr));
}

// ---------------------------------------------------------------------------
// Kernel A: g_xp[r][j] = 0.1*(sum_i input[r][i]*Wx[j][i] + b[j])
// EXACT round-7 scalar FFMA2 kernel (measured 163.9us).
// ---------------------------------------------------------------------------
#define INS_STRIDE 68
__global__ void __launch_bounds__(256, 3) xp_gemm_kernel(
    const float* __restrict__ inp,   // [B*T, DI]
    const float* __restrict__ Wx,    // [H, DI]
    const float* __restrict__ bias)  // [H]
{
    extern __shared__ __align__(16) float smem[];
    float* Wx_s = smem;                 // [i][j]  (pre-scaled by 0.1)
    float* in_s = smem + DI_ * H_;      // [i][r]

    const int tid = threadIdx.x;
    const int tx  = tid & 31;   // col quad (active tx < 25)
    const int ty  = tid >> 5;   // warp id (0..7) -> rows 8*ty..8*ty+7

    for (int idx = tid; idx < DI_ * H_; idx += 256) {
        int j = idx / DI_;
        int i = idx - j * DI_;
        Wx_s[i * H_ + j] = 0.1f * Wx[idx];
    }

    float bv[4] = {0.f, 0.f, 0.f, 0.f};
    if (tx < 25) {
#pragma unroll
        for (int c = 0; c < 4; c++) bv[c] = 0.1f * bias[4 * tx + c];
    }

    const int ntiles = (B_ * T_) / 64;   // 4096
    for (int tile = blockIdx.x; tile < ntiles; tile += gridDim.x) {
        __syncthreads();
        const int rbase = tile * 64;
        for (int idx = tid; idx < 64 * DI_; idx += 256) {
            int r = idx / DI_;
            int i = idx - r * DI_;
            in_s[i * INS_STRIDE + r] = inp[(size_t)(rbase + r) * DI_ + i];
        }
        __syncthreads();

        if (tx < 25) {
            ull acc[4][4];
#pragma unroll
            for (int p = 0; p < 4; p++)
#pragma unroll
                for (int c = 0; c < 4; c++) acc[p][c] = dup2(bv[c]);

#pragma unroll 4
            for (int i = 0; i < DI_; i++) {
                ulonglong2 ap0 = *(const ulonglong2*)(in_s + i * INS_STRIDE + 8 * ty);
                ulonglong2 ap1 = *(const ulonglong2*)(in_s + i * INS_STRIDE + 8 * ty + 4);
                float4 wv = *(const float4*)(Wx_s + i * H_ + 4 * tx);
                ull w0 = dup2(wv.x), w1 = dup2(wv.y), w2 = dup2(wv.z), w3 = dup2(wv.w);
                acc[0][0] = fma2(ap0.x, w0, acc[0][0]);
                acc[0][1] = fma2(ap0.x, w1, acc[0][1]);
                acc[0][2] = fma2(ap0.x, w2, acc[0][2]);
                acc[0][3] = fma2(ap0.x, w3, acc[0][3]);
                acc[1][0] = fma2(ap0.y, w0, acc[1][0]);
                acc[1][1] = fma2(ap0.y, w1, acc[1][1]);
                acc[1][2] = fma2(ap0.y, w2, acc[1][2]);
                acc[1][3] = fma2(ap0.y, w3, acc[1][3]);
                acc[2][0] = fma2(ap1.x, w0, acc[2][0]);
                acc[2][1] = fma2(ap1.x, w1, acc[2][1]);
                acc[2][2] = fma2(ap1.x, w2, acc[2][2]);
                acc[2][3] = fma2(ap1.x, w3, acc[2][3]);
                acc[3][0] = fma2(ap1.y, w0, acc[3][0]);
                acc[3][1] = fma2(ap1.y, w1, acc[3][1]);
                acc[3][2] = fma2(ap1.y, w2, acc[3][2]);
                acc[3][3] = fma2(ap1.y, w3, acc[3][3]);
            }
#pragma unroll
            for (int p = 0; p < 4; p++) {
                float2 c0 = u2f(acc[p][0]);
                float2 c1 = u2f(acc[p][1]);
                float2 c2 = u2f(acc[p][2]);
                float2 c3 = u2f(acc[p][3]);
                int re = rbase + 8 * ty + 2 * p;
                float4 oe; oe.x = c0.x; oe.y = c1.x; oe.z = c2.x; oe.w = c3.x;
                float4 oo; oo.x = c0.y; oo.y = c1.y; oo.z = c2.y; oo.w = c3.y;
                *(float4*)(g_xp + (size_t)re * H_ + 4 * tx)       = oe;
                *(float4*)(g_xp + (size_t)(re + 1) * H_ + 4 * tx) = oo;
            }
        }
    }
}

// ---------------------------------------------------------------------------
// Kernel B: sequential scan, K-SPLIT. 256 CTAs x 224 threads, 2 chains/CTA.
// Thread u: j = u>>1, half = u&1 (active u<200). wk[25] = 0.1*W[j][50h..50h+49]
// in registers (shared across both chains). Per chain per step: 13 LDS of h
// + 25 fma2; partner halves combine with one shfl_xor. Both lanes track both
// chains' ah (identical values). half0 lane stores chain0, half1 chain1.
// h double-buffered in smem with 6-float pad so each half-section is
// 16B-aligned. xp/noise via depth-4 cp.async ring.
// ---------------------------------------------------------------------------
__global__ void __launch_bounds__(224, 2) scan_kernel(
    const float* __restrict__ noise,   // [B, T, H]
    const float* __restrict__ Wh,      // [H, H]
    const float* __restrict__ ah0,     // [H]
    float* __restrict__ hstore)        // [B, T, H]
{
    __shared__ __align__(16) float hs[2][2][112];     // [buf][chain][padded h]
    __shared__ __align__(16) float rxp[4][112][2];    // [slot][j][chain]
    __shared__ __align__(16) float rnz[4][112][2];

    const int u    = threadIdx.x;
    const int j    = u >> 1;
    const int half = u & 1;
    const bool act = (u < 200);
    const int c0   = blockIdx.x * 2;

    // de-phase co-resident CTAs
    {
        long long lim = (long long)((blockIdx.x & 1) * 300);
        long long s0 = clock64();
        while (clock64() - s0 < lim) {}
    }

    // 0.1 * W[j][50*half .. 50*half+49] -> 25 packed b64 regs
    ull wk[25];
#pragma unroll
    for (int i = 0; i < 25; i++) wk[i] = 0;
    if (act) {
        const float2* wr = (const float2*)(Wh + j * H_ + 50 * half);
#pragma unroll
        for (int i = 0; i < 25; i++) {
            float2 v = wr[i];
            float2 s; s.x = 0.1f * v.x; s.y = 0.1f * v.y;
            wk[i] = *(ull*)&s;
        }
    }

    float ahA = 0.f, ahB = 0.f;
    if (act) {
        float a0 = ah0[j];
        ahA = a0; ahB = a0;
        float h0 = tanhf(fmaxf(a0, 0.f));
        int slot = (j < 50) ? j : j + 6;
        hs[0][half][slot] = h0;     // (j,0) covers chain0, (j,1) covers chain1
    }

    // streaming pointers: thread (j,half) produces chain (c0+half), column j
    const float* my_xp = g_xp  + (size_t)(c0 + half) * (T_ * H_) + j;
    const float* my_nz = noise + (size_t)(c0 + half) * (T_ * H_) + j;
    float* hstA = hstore + (size_t)(c0 + 0) * (T_ * H_) + j;
    float* hstB = hstore + (size_t)(c0 + 1) * (T_ * H_) + j;

    unsigned rxp_a = (unsigned)__cvta_generic_to_shared(rxp);
    unsigned rnz_a = (unsigned)__cvta_generic_to_shared(rnz);

#pragma unroll
    for (int p = 0; p < 3; p++) {
        if (act) {
            cp_async4(rxp_a + 4u * ((p * 112 + j) * 2 + half), my_xp + (size_t)p * H_);
            cp_async4(rnz_a + 4u * ((p * 112 + j) * 2 + half), my_nz + (size_t)p * H_);
        }
        asm volatile("cp.async.commit_group;");
    }
    __syncthreads();

    int buf = 0;
    for (int t = 0; t < T_; t++) {
        if (act && t + 3 < T_) {
            int s = (t + 3) & 3;
            cp_async4(rxp_a + 4u * ((s * 112 + j) * 2 + half), my_xp + (size_t)(t + 3) * H_);
            cp_async4(rnz_a + 4u * ((s * 112 + j) * 2 + half), my_nz + (size_t)(t + 3) * H_);
        }
        asm volatile("cp.async.commit_group;");
        asm volatile("cp.async.wait_group 3;");   // slot t complete

        // matvec partials for both chains (all lanes execute; inactive = zeros)
        const ulonglong2* h0p = (const ulonglong2*)(&hs[buf][0][half * 56]);
        const ulonglong2* h1p = (const ulonglong2*)(&hs[buf][1][half * 56]);
        ull a0 = 0, b0 = 0, a1 = 0, b1 = 0;
#pragma unroll
        for (int i = 0; i < 12; i++) {
            ulonglong2 v0 = h0p[i];
            ulonglong2 v1 = h1p[i];
            a0 = fma2(v0.x, wk[2 * i],     a0);
            b0 = fma2(v0.y, wk[2 * i + 1], b0);
            a1 = fma2(v1.x, wk[2 * i],     a1);
            b1 = fma2(v1.y, wk[2 * i + 1], b1);
        }
        {
            ull l0 = *(const ull*)(h0p + 12);
            ull l1 = *(const ull*)(h1p + 12);
            a0 = fma2(l0, wk[24], a0);
            a1 = fma2(l1, wk[24], a1);
        }
        float2 s0 = u2f(add2(a0, b0));
        float2 s1 = u2f(add2(a1, b1));
        float p0 = s0.x + s0.y;
        float p1 = s1.x + s1.y;
        p0 += __shfl_xor_sync(0xffffffffu, p0, 1);   // combine k-halves
        p1 += __shfl_xor_sync(0xffffffffu, p1, 1);

        // xp/noise for both chains (lane pair reads same addr -> broadcast)
        float2 xv = *(const float2*)&rxp[t & 3][j][0];
        float2 nv = *(const float2*)&rnz[t & 3][j][0];

        ahA = fmaf(0.9f, ahA, p0 + xv.x);
        ahB = fmaf(0.9f, ahB, p1 + xv.y);
        float xA = fmaxf(ahA, 0.f);
        float xB = fmaxf(ahB, 0.f);
        float eA = __expf(-2.f * xA);
        float eB = __expf(-2.f * xB);
        float hA = __fdividef(1.f - eA, 1.f + eA) + nv.x;
        float hB = __fdividef(1.f - eB, 1.f + eB) + nv.y;

        if (act) {
            int slot = (j < 50) ? j : j + 6;
            if (half == 0) {
                hs[buf ^ 1][0][slot] = hA;
                hstA[(size_t)t * H_] = hA;
            } else {
                hs[buf ^ 1][1][slot] = hB;
                hstB[(size_t)t * H_] = hB;
            }
        }
        buf ^= 1;
        __syncthreads();
    }
}

// ---------------------------------------------------------------------------
// Kernel C: output[r][d] = sum_j hstore[r][j] * W_y[d][j]
// ---------------------------------------------------------------------------
__global__ void __launch_bounds__(256) outproj_kernel(
    const float* __restrict__ hst,   // [B*T, H]
    const float* __restrict__ Wy,    // [DO, H]
    float* __restrict__ out)         // [B*T, DO]
{
    __shared__ float wy_s[DO_ * H_];
    const int tid = threadIdx.x;
    for (int idx = tid; idx < DO_ * H_; idx += 256) wy_s[idx] = Wy[idx];
    __syncthreads();

    const int lane = tid & 31;
    const int w    = tid >> 5;
    const size_t row = (size_t)blockIdx.x * 8 + w;

    float a0 = 0.f, a1 = 0.f;
    for (int j = lane; j < H_; j += 32) {
        float h = hst[row * H_ + j];
        a0 = fmaf(h, wy_s[j],      a0);
        a1 = fmaf(h, wy_s[H_ + j], a1);
    }
#pragma unroll
    for (int off = 16; off > 0; off >>= 1) {
        a0 += __shfl_down_sync(0xffffffffu, a0, off);
        a1 += __shfl_down_sync(0xffffffffu, a1, off);
    }
    if (lane == 0) {
        out[row * DO_ + 0] = a0;
        out[row * DO_ + 1] = a1;
    }
}

// ---------------------------------------------------------------------------
extern "C" void kernel_launch(void* const* d_in, const int* in_sizes, int n_in,
                              void* d_out, int out_size)
{
    const float* inp   = (const float*)d_in[0];  // [B,T,DI]
    const float* noise = (const float*)d_in[1];  // [B,T,H]
    const float* Wx    = (const float*)d_in[2];  // [H,DI]
    const float* bias  = (const float*)d_in[3];  // [H]
    const float* Wh    = (const float*)d_in[4];  // [H,H]
    const float* Wy    = (const float*)d_in[5];  // [DO,H]
    const float* ah0   = (const float*)d_in[6];  // [H]

    float* out    = (float*)d_out;                  // [B,T,DO] first
    float* hstore = out + (size_t)B_ * T_ * DO_;    // [B,T,H] second

    const int xp_smem = (DI_ * H_ + DI_ * INS_STRIDE) * (int)sizeof(float);  // 67872 B
    static int attr_done = 0;
    if (!attr_done) {
        cudaFuncSetAttribute(xp_gemm_kernel,
                             cudaFuncAttributeMaxDynamicSharedMemorySize, xp_smem);
        cudaFuncSetAttribute(xp_gemm_kernel,
                             cudaFuncAttributePreferredSharedMemoryCarveout,
                             cudaSharedmemCarveoutMaxShared);
        attr_done = 1;
    }

    xp_gemm_kernel<<<1024, 256, xp_smem>>>(inp, Wx, bias);
    scan_kernel<<<B_ / 2, 224>>>(noise, Wh, ah0, hstore);
    outproj_kernel<<<(B_ * T_) / 8, 256>>>(hstore, Wy, out);
}